// round 1
// baseline (speedup 1.0000x reference)
#include <cuda_runtime.h>

// Problem constants (B=4, L=2048, H=16, D=64 — fixed by the dataset)
#define Bc 4
#define Hc 16
#define Lc 2048
#define Dc 64
#define BM 64
#define BN 64
#define NTHREADS 256

// Shared memory layout (floats):
//   Qs : BM x Dc        (stride 64, broadcast reads -> no pad needed)
//   KP : BN x (Dc+1)    (K tile read as [col][k] needs pad; reused for P)
//   Vs : BN x Dc        (stride 64, 2-way worst case -> acceptable)
#define QS_STRIDE Dc
#define KP_STRIDE (Dc + 1)
#define VS_STRIDE Dc
#define SMEM_FLOATS (BM * QS_STRIDE + BN * KP_STRIDE + BN * VS_STRIDE)
#define SMEM_BYTES (SMEM_FLOATS * 4)

__global__ void __launch_bounds__(NTHREADS)
logsparse_flash_kernel(const float* __restrict__ Q,
                       const float* __restrict__ K,
                       const float* __restrict__ V,
                       float* __restrict__ O) {
    extern __shared__ float smem[];
    float* Qs = smem;                          // BM * 64
    float* KP = Qs + BM * QS_STRIDE;           // BN * 65  (K tile, then P tile)
    float* Vs = KP + BN * KP_STRIDE;           // BN * 64

    // Heavy blocks (large m) launch first: flatten triangular imbalance.
    const int m  = (int)gridDim.x - 1 - (int)blockIdx.x;
    const int bh = blockIdx.y;
    const int b  = bh / Hc;
    const int h  = bh % Hc;

    const int tid = threadIdx.x;
    const int tx  = tid & 15;       // 16 col-threads
    const int ty  = tid >> 4;       // 16 row-threads
    const int r0  = ty * 4;
    const int c0  = tx * 4;

    const size_t rowstride = (size_t)Hc * Dc;  // 1024 floats between seq positions
    const float* Qg = Q + ((size_t)b * Lc + (size_t)m * BM) * rowstride + (size_t)h * Dc;
    const float* Kg = K + (size_t)b * Lc * rowstride + (size_t)h * Dc;
    const float* Vg = V + (size_t)b * Lc * rowstride + (size_t)h * Dc;

    // ---- Load Q tile (64x64 floats, float4-vectorized, coalesced) ----
#pragma unroll
    for (int it = 0; it < (BM * Dc / 4) / NTHREADS; ++it) {   // 4 iters
        int idx = tid + it * NTHREADS;
        int r   = idx >> 4;          // 0..63
        int c4  = idx & 15;          // 0..15 (float4 index)
        float4 v = *(const float4*)(Qg + (size_t)r * rowstride + c4 * 4);
        float* dst = Qs + r * QS_STRIDE + c4 * 4;
        dst[0] = v.x; dst[1] = v.y; dst[2] = v.z; dst[3] = v.w;
    }

    // ---- Online-softmax state (rows replicated across the 16 tx threads) ----
    float m_i[4], l_i[4], o[4][4];
#pragma unroll
    for (int i = 0; i < 4; ++i) {
        m_i[i] = -1e30f;
        l_i[i] = 0.f;
#pragma unroll
        for (int j = 0; j < 4; ++j) o[i][j] = 0.f;
    }

    for (int n = 0; n <= m; ++n) {
        __syncthreads();   // previous iter done with KP (P) and Vs
        // ---- Load K and V tiles for column block n ----
#pragma unroll
        for (int it = 0; it < 4; ++it) {
            int idx = tid + it * NTHREADS;
            int r   = idx >> 4;
            int c4  = idx & 15;
            const float* srcK = Kg + ((size_t)(n * BN + r)) * rowstride + c4 * 4;
            float4 kv = *(const float4*)srcK;
            float* dk = KP + r * KP_STRIDE + c4 * 4;
            dk[0] = kv.x; dk[1] = kv.y; dk[2] = kv.z; dk[3] = kv.w;
            const float* srcV = Vg + ((size_t)(n * BN + r)) * rowstride + c4 * 4;
            float4 vv = *(const float4*)srcV;
            float* dv = Vs + r * VS_STRIDE + c4 * 4;
            dv[0] = vv.x; dv[1] = vv.y; dv[2] = vv.z; dv[3] = vv.w;
        }
        __syncthreads();

        // ---- S = Q * K^T  (4x4 microtile per thread) ----
        float s[4][4];
#pragma unroll
        for (int i = 0; i < 4; ++i)
#pragma unroll
            for (int j = 0; j < 4; ++j) s[i][j] = 0.f;

#pragma unroll
        for (int k = 0; k < Dc; ++k) {
            float a[4], bb[4];
#pragma unroll
            for (int i = 0; i < 4; ++i) a[i] = Qs[(r0 + i) * QS_STRIDE + k];
#pragma unroll
            for (int j = 0; j < 4; ++j) bb[j] = KP[(c0 + j) * KP_STRIDE + k];
#pragma unroll
            for (int i = 0; i < 4; ++i)
#pragma unroll
                for (int j = 0; j < 4; ++j)
                    s[i][j] = fmaf(a[i], bb[j], s[i][j]);
        }

        // ---- Causal mask on the diagonal tile ----
        if (n == m) {
#pragma unroll
            for (int i = 0; i < 4; ++i)
#pragma unroll
                for (int j = 0; j < 4; ++j)
                    if (c0 + j > r0 + i) s[i][j] = -1e30f;
        }

        // ---- Online softmax update ----
#pragma unroll
        for (int i = 0; i < 4; ++i) {
            float tmax = fmaxf(fmaxf(s[i][0], s[i][1]), fmaxf(s[i][2], s[i][3]));
#pragma unroll
            for (int off = 1; off < 16; off <<= 1)
                tmax = fmaxf(tmax, __shfl_xor_sync(0xffffffffu, tmax, off));
            float mn = fmaxf(m_i[i], tmax);
            float sc = __expf(m_i[i] - mn);
            float rs = 0.f;
#pragma unroll
            for (int j = 0; j < 4; ++j) {
                float p = __expf(s[i][j] - mn);
                s[i][j] = p;
                rs += p;
            }
#pragma unroll
            for (int off = 1; off < 16; off <<= 1)
                rs += __shfl_xor_sync(0xffffffffu, rs, off);
            l_i[i] = l_i[i] * sc + rs;
            m_i[i] = mn;
#pragma unroll
            for (int j = 0; j < 4; ++j) o[i][j] *= sc;
        }

        __syncthreads();   // everyone done reading K from KP
        // ---- Stage P into KP (K is dead) ----
#pragma unroll
        for (int i = 0; i < 4; ++i)
#pragma unroll
            for (int j = 0; j < 4; ++j)
                KP[(r0 + i) * KP_STRIDE + (c0 + j)] = s[i][j];
        __syncthreads();

        // ---- O += P * V  (4x4 microtile per thread over D) ----
#pragma unroll
        for (int c = 0; c < BN; ++c) {
            float a[4], bb[4];
#pragma unroll
            for (int i = 0; i < 4; ++i) a[i] = KP[(r0 + i) * KP_STRIDE + c];
#pragma unroll
            for (int j = 0; j < 4; ++j) bb[j] = Vs[c * VS_STRIDE + c0 + j];
#pragma unroll
            for (int i = 0; i < 4; ++i)
#pragma unroll
                for (int j = 0; j < 4; ++j)
                    o[i][j] = fmaf(a[i], bb[j], o[i][j]);
        }
    }

    // ---- Epilogue: normalize and store (output layout [B, H, L, D]) ----
    float* Og = O + ((size_t)(b * Hc + h) * Lc + (size_t)m * BM) * Dc;
#pragma unroll
    for (int i = 0; i < 4; ++i) {
        float inv = 1.f / l_i[i];
        float4 v;
        v.x = o[i][0] * inv;
        v.y = o[i][1] * inv;
        v.z = o[i][2] * inv;
        v.w = o[i][3] * inv;
        *(float4*)(Og + (size_t)(r0 + i) * Dc + c0) = v;
    }
}

extern "C" void kernel_launch(void* const* d_in, const int* in_sizes, int n_in,
                              void* d_out, int out_size) {
    const float* Q = (const float*)d_in[0];
    const float* K = (const float*)d_in[1];
    const float* V = (const float*)d_in[2];
    // d_in[3] (attn_mask) is unused by the reference module.
    float* O = (float*)d_out;

    // 48.5 KB dynamic smem: opt in above the 48 KB default. Attribute set is
    // idempotent, not a stream op, and not an allocation -> capture-safe.
    cudaFuncSetAttribute(logsparse_flash_kernel,
                         cudaFuncAttributeMaxDynamicSharedMemorySize, SMEM_BYTES);

    dim3 grid(Lc / BM, Bc * Hc);
    logsparse_flash_kernel<<<grid, NTHREADS, SMEM_BYTES>>>(Q, K, V, O);
}

// round 2
// speedup vs baseline: 1.1283x; 1.1283x over previous
#include <cuda_runtime.h>

// Problem constants (B=4, L=2048, H=16, D=64 — fixed by the dataset)
#define Bc 4
#define Hc 16
#define Lc 2048
#define Dc 64
#define BM 128
#define BN 128
#define NT 256

// Shared layouts (floats):
//   Qt : [64 k][BM rows]   stride QTS (k-major: a-loads are tx-broadcast float4)
//   Kt : [64 k][BN cols]   stride KTS (k-major: b-loads are packed b64, N=1)
//   Pt : [BN col][BM rows] stride PTS (P staged transposed: PV a-loads broadcast)
//   Vs : [BN c][64 d]      stride VSS
#define QTS 132
#define KTS 130
#define PTS 132
#define VSS 64
#define SMEM_FLOATS (64 * QTS + 64 * KTS + BN * PTS + BN * VSS)
#define SMEM_BYTES (SMEM_FLOATS * 4)

typedef unsigned long long ull;

__device__ __forceinline__ float f2lo(ull v) { return __uint_as_float((unsigned)v); }
__device__ __forceinline__ float f2hi(ull v) { return __uint_as_float((unsigned)(v >> 32)); }
__device__ __forceinline__ ull fpack(float x, float y) {
    ull r; asm("mov.b64 %0, {%1, %2};" : "=l"(r) : "f"(x), "f"(y)); return r;
}
__device__ __forceinline__ void ffma2(ull& d, ull a, ull b) {
    asm("fma.rn.f32x2 %0, %1, %2, %0;" : "+l"(d) : "l"(a), "l"(b));
}
__device__ __forceinline__ ull fmul2(ull a, ull b) {
    ull r; asm("mul.rn.f32x2 %0, %1, %2;" : "=l"(r) : "l"(a), "l"(b)); return r;
}

__global__ void __launch_bounds__(NT, 1)
logsparse_flash2_kernel(const float* __restrict__ Q,
                        const float* __restrict__ K,
                        const float* __restrict__ V,
                        float* __restrict__ O) {
    extern __shared__ float sm[];
    float* Qt = sm;                  // 64 x QTS
    float* Kt = Qt + 64 * QTS;       // 64 x KTS
    float* Pt = Kt + 64 * KTS;       // BN x PTS
    float* Vs = Pt + BN * PTS;       // BN x VSS

    // Heavy blocks (large m) first: flatten triangular imbalance.
    const int m  = (int)gridDim.x - 1 - (int)blockIdx.x;
    const int bh = blockIdx.y;
    const int b  = bh >> 4;
    const int h  = bh & 15;

    const int tid = threadIdx.x;
    const int tx  = tid & 15;
    const int ty  = tid >> 4;
    const int r0  = ty * 8;          // 8 query rows per thread
    const int ctx = 2 * tx;          // col/d pair base; thread cols: 32p + ctx (+1)

    const size_t rs = (size_t)Hc * Dc;   // 1024 floats between seq positions
    const float* Qg = Q + ((size_t)b * Lc + (size_t)m * BM) * rs + (size_t)h * Dc;
    const float* Kg = K + (size_t)b * Lc * rs + (size_t)h * Dc;
    const float* Vg = V + (size_t)b * Lc * rs + (size_t)h * Dc;

    // ---- Load Q tile transposed into Qt[k][row] ----
#pragma unroll
    for (int it = 0; it < 8; ++it) {
        int idx = tid + it * NT;
        int r = idx >> 4, c4 = idx & 15;
        float4 v = *(const float4*)(Qg + (size_t)r * rs + c4 * 4);
        Qt[(c4 * 4 + 0) * QTS + r] = v.x;
        Qt[(c4 * 4 + 1) * QTS + r] = v.y;
        Qt[(c4 * 4 + 2) * QTS + r] = v.z;
        Qt[(c4 * 4 + 3) * QTS + r] = v.w;
    }

    // ---- Online-softmax state ----
    ull   o2[8][2];
    float m_i[8], l_i[8];
#pragma unroll
    for (int i = 0; i < 8; ++i) {
        m_i[i] = -1e30f; l_i[i] = 0.f;
        o2[i][0] = 0ull; o2[i][1] = 0ull;
    }

    for (int n = 0; n <= m; ++n) {
        __syncthreads();   // prior iter done with Kt/Vs/Pt
        // ---- Load K (transposed) and V tiles for column block n ----
#pragma unroll
        for (int it = 0; it < 8; ++it) {
            int idx = tid + it * NT;
            int r = idx >> 4, c4 = idx & 15;
            const float* kp = Kg + ((size_t)(n * BN + r)) * rs + c4 * 4;
            float4 kv = *(const float4*)kp;
            Kt[(c4 * 4 + 0) * KTS + r] = kv.x;
            Kt[(c4 * 4 + 1) * KTS + r] = kv.y;
            Kt[(c4 * 4 + 2) * KTS + r] = kv.z;
            Kt[(c4 * 4 + 3) * KTS + r] = kv.w;
            const float* vp = Vg + ((size_t)(n * BN + r)) * rs + c4 * 4;
            float4 vv = *(const float4*)vp;
            *(float4*)(Vs + r * VSS + c4 * 4) = vv;
        }
        __syncthreads();

        // ---- S = Q * K^T : 8x8 microtile, packed f32x2 over column pairs ----
        ull s2[8][4];
#pragma unroll
        for (int i = 0; i < 8; ++i)
#pragma unroll
            for (int p = 0; p < 4; ++p) s2[i][p] = 0ull;

#pragma unroll 8
        for (int k = 0; k < Dc; ++k) {
            float4 qa = *(const float4*)(Qt + k * QTS + r0);
            float4 qb = *(const float4*)(Qt + k * QTS + r0 + 4);
            ull a2[8];
            a2[0] = fpack(qa.x, qa.x); a2[1] = fpack(qa.y, qa.y);
            a2[2] = fpack(qa.z, qa.z); a2[3] = fpack(qa.w, qa.w);
            a2[4] = fpack(qb.x, qb.x); a2[5] = fpack(qb.y, qb.y);
            a2[6] = fpack(qb.z, qb.z); a2[7] = fpack(qb.w, qb.w);
            ull bb[4];
#pragma unroll
            for (int p = 0; p < 4; ++p)
                bb[p] = *(const ull*)(Kt + k * KTS + 32 * p + ctx);
#pragma unroll
            for (int i = 0; i < 8; ++i)
#pragma unroll
                for (int p = 0; p < 4; ++p)
                    ffma2(s2[i][p], a2[i], bb[p]);
        }

        // ---- Online softmax (registers only) ----
        const bool diag = (n == m);
#pragma unroll
        for (int i = 0; i < 8; ++i) {
            float pv[8];
#pragma unroll
            for (int p = 0; p < 4; ++p) {
                pv[2 * p]     = f2lo(s2[i][p]);
                pv[2 * p + 1] = f2hi(s2[i][p]);
            }
            if (diag) {
#pragma unroll
                for (int p = 0; p < 4; ++p) {
                    if (32 * p + ctx     > r0 + i) pv[2 * p]     = -1e30f;
                    if (32 * p + ctx + 1 > r0 + i) pv[2 * p + 1] = -1e30f;
                }
            }
            float tmax = pv[0];
#pragma unroll
            for (int e = 1; e < 8; ++e) tmax = fmaxf(tmax, pv[e]);
#pragma unroll
            for (int off = 1; off < 16; off <<= 1)
                tmax = fmaxf(tmax, __shfl_xor_sync(0xffffffffu, tmax, off));
            float mn = fmaxf(m_i[i], tmax);
            float sc = __expf(m_i[i] - mn);
            float rsum = 0.f;
#pragma unroll
            for (int e = 0; e < 8; ++e) {
                pv[e] = __expf(pv[e] - mn);
                rsum += pv[e];
            }
#pragma unroll
            for (int off = 1; off < 16; off <<= 1)
                rsum += __shfl_xor_sync(0xffffffffu, rsum, off);
            l_i[i] = l_i[i] * sc + rsum;
            m_i[i] = mn;
            ull sc2 = fpack(sc, sc);
            o2[i][0] = fmul2(o2[i][0], sc2);
            o2[i][1] = fmul2(o2[i][1], sc2);
#pragma unroll
            for (int p = 0; p < 4; ++p)
                s2[i][p] = fpack(pv[2 * p], pv[2 * p + 1]);
        }

        // ---- Stage P transposed: Pt[col][row] ----
#pragma unroll
        for (int p = 0; p < 4; ++p) {
            int c = 32 * p + ctx;
            float4 lo0 = make_float4(f2lo(s2[0][p]), f2lo(s2[1][p]), f2lo(s2[2][p]), f2lo(s2[3][p]));
            float4 lo1 = make_float4(f2lo(s2[4][p]), f2lo(s2[5][p]), f2lo(s2[6][p]), f2lo(s2[7][p]));
            *(float4*)(Pt + c * PTS + r0)     = lo0;
            *(float4*)(Pt + c * PTS + r0 + 4) = lo1;
            float4 hi0 = make_float4(f2hi(s2[0][p]), f2hi(s2[1][p]), f2hi(s2[2][p]), f2hi(s2[3][p]));
            float4 hi1 = make_float4(f2hi(s2[4][p]), f2hi(s2[5][p]), f2hi(s2[6][p]), f2hi(s2[7][p]));
            *(float4*)(Pt + (c + 1) * PTS + r0)     = hi0;
            *(float4*)(Pt + (c + 1) * PTS + r0 + 4) = hi1;
        }
        __syncthreads();

        // ---- O += P * V : packed over d pairs ----
#pragma unroll 8
        for (int c = 0; c < BN; ++c) {
            float4 pa = *(const float4*)(Pt + c * PTS + r0);
            float4 pb = *(const float4*)(Pt + c * PTS + r0 + 4);
            ull a2[8];
            a2[0] = fpack(pa.x, pa.x); a2[1] = fpack(pa.y, pa.y);
            a2[2] = fpack(pa.z, pa.z); a2[3] = fpack(pa.w, pa.w);
            a2[4] = fpack(pb.x, pb.x); a2[5] = fpack(pb.y, pb.y);
            a2[6] = fpack(pb.z, pb.z); a2[7] = fpack(pb.w, pb.w);
            ull vb0 = *(const ull*)(Vs + c * VSS + ctx);
            ull vb1 = *(const ull*)(Vs + c * VSS + 32 + ctx);
#pragma unroll
            for (int i = 0; i < 8; ++i) {
                ffma2(o2[i][0], a2[i], vb0);
                ffma2(o2[i][1], a2[i], vb1);
            }
        }
    }

    // ---- Epilogue: normalize, store (output [B, H, L, D]) ----
    float* Og = O + ((size_t)(b * Hc + h) * Lc + (size_t)m * BM) * Dc;
#pragma unroll
    for (int i = 0; i < 8; ++i) {
        float inv = 1.f / l_i[i];
        float2 v0, v1;
        v0.x = f2lo(o2[i][0]) * inv; v0.y = f2hi(o2[i][0]) * inv;
        v1.x = f2lo(o2[i][1]) * inv; v1.y = f2hi(o2[i][1]) * inv;
        *(float2*)(Og + (size_t)(r0 + i) * Dc + ctx)      = v0;
        *(float2*)(Og + (size_t)(r0 + i) * Dc + 32 + ctx) = v1;
    }
}

extern "C" void kernel_launch(void* const* d_in, const int* in_sizes, int n_in,
                              void* d_out, int out_size) {
    const float* Q = (const float*)d_in[0];
    const float* K = (const float*)d_in[1];
    const float* V = (const float*)d_in[2];
    float* O = (float*)d_out;

    cudaFuncSetAttribute(logsparse_flash2_kernel,
                         cudaFuncAttributeMaxDynamicSharedMemorySize, SMEM_BYTES);

    dim3 grid(Lc / BM, Bc * Hc);
    logsparse_flash2_kernel<<<grid, NT, SMEM_BYTES>>>(Q, K, V, O);
}

// round 3
// speedup vs baseline: 1.1783x; 1.0443x over previous
#include <cuda_runtime.h>
#include <cstdint>

// Problem constants (B=4, L=2048, H=16, D=64 — fixed by the dataset)
#define Bc 4
#define Hc 16
#define Lc 2048
#define Dc 64
#define BM 128
#define BN 64
#define NT 256

// Shared layouts (floats), strides chosen for conflict-free fragment LDS:
//   Ks : [64 c][64 k] stride 68  -> bank(4c+k): S B-frag lanes (g,tg) map 4g+tg distinct
//   Vs : [64 c][64 d] stride 72  -> bank(8c+d): PV B-frag lanes map 8tg+g distinct
//   Ps : 8 warps x [16 r][64 c] stride 68 -> A-frag lanes map 4g+tg distinct
#define KS 68
#define VS 72
#define PS 68
#define SMEM_FLOATS (64 * KS + 64 * VS + 8 * 16 * PS)
#define SMEM_BYTES (SMEM_FLOATS * 4)

__device__ __forceinline__ void tf32_split(float x, uint32_t& hi, uint32_t& lo) {
    uint32_t h;
    asm("cvt.rna.tf32.f32 %0, %1;" : "=r"(h) : "f"(x));
    hi = h;
    float lf = x - __uint_as_float(h);
    asm("cvt.rna.tf32.f32 %0, %1;" : "=r"(lo) : "f"(lf));
}

__device__ __forceinline__ void mma8(float* d,
                                     uint32_t a0, uint32_t a1, uint32_t a2, uint32_t a3,
                                     uint32_t b0, uint32_t b1) {
    asm("mma.sync.aligned.m16n8k8.row.col.f32.tf32.tf32.f32 "
        "{%0,%1,%2,%3},{%4,%5,%6,%7},{%8,%9},{%0,%1,%2,%3};"
        : "+f"(d[0]), "+f"(d[1]), "+f"(d[2]), "+f"(d[3])
        : "r"(a0), "r"(a1), "r"(a2), "r"(a3), "r"(b0), "r"(b1));
}

__global__ void __launch_bounds__(NT)
logsparse_flash_tc_kernel(const float* __restrict__ Q,
                          const float* __restrict__ K,
                          const float* __restrict__ V,
                          float* __restrict__ O) {
    extern __shared__ float smf[];
    float* Ks = smf;                    // 64 x KS
    float* Vs = Ks + 64 * KS;           // 64 x VS
    float* Pw = Vs + 64 * VS + (threadIdx.x >> 5) * (16 * PS);  // per-warp 16 x PS

    // Heavy blocks (large m) first: flatten triangular imbalance.
    const int m  = (int)gridDim.x - 1 - (int)blockIdx.x;
    const int bh = blockIdx.y;
    const int b  = bh >> 4;
    const int h  = bh & 15;

    const int tid  = threadIdx.x;
    const int wid  = tid >> 5;
    const int lane = tid & 31;
    const int g    = lane >> 2;     // fragment group id (0..7)
    const int tg   = lane & 3;      // thread-in-group (0..3)

    const int R0    = wid * 16;               // warp's local row base within tile
    const int gRowA = m * BM + R0 + g;        // global query row (A)
    const int gRowB = gRowA + 8;              // global query row (B)

    const size_t rs = (size_t)Hc * Dc;        // 1024 floats between seq positions
    const float* Qg = Q + ((size_t)b * Lc + (size_t)m * BM) * rs + (size_t)h * Dc;
    const float* Kg = K + (size_t)b * Lc * rs + (size_t)h * Dc;
    const float* Vg = V + (size_t)b * Lc * rs + (size_t)h * Dc;

    // ---- Load Q fragments once (loop-invariant). A-frag layout m16k8. ----
    float qf[8][4];
#pragma unroll
    for (int cc = 0; cc < 8; ++cc) {
        int k0 = 8 * cc + tg;
        qf[cc][0] = Qg[(size_t)(R0 + g)     * rs + k0];
        qf[cc][1] = Qg[(size_t)(R0 + g + 8) * rs + k0];
        qf[cc][2] = Qg[(size_t)(R0 + g)     * rs + k0 + 4];
        qf[cc][3] = Qg[(size_t)(R0 + g + 8) * rs + k0 + 4];
    }

    // ---- Online-softmax state + O accumulators (C-frag layout) ----
    float o[8][4];
    float mA = -1e30f, mB = -1e30f, lA = 0.f, lB = 0.f;
#pragma unroll
    for (int j = 0; j < 8; ++j) { o[j][0] = o[j][1] = o[j][2] = o[j][3] = 0.f; }

    const int nend = (m * BM + BM - 1) / BN;   // inclusive last col-block

    for (int n = 0; n <= nend; ++n) {
        __syncthreads();   // prior iter done reading Ks/Vs
        // ---- Load K and V tiles (coalesced float4) ----
#pragma unroll
        for (int it = 0; it < 4; ++it) {
            int idx = tid + it * NT;           // 0..1023
            int r = idx >> 4, c4 = idx & 15;
            float4 kv = *(const float4*)(Kg + ((size_t)(n * BN + r)) * rs + c4 * 4);
            *(float4*)(Ks + r * KS + c4 * 4) = kv;
            float4 vv = *(const float4*)(Vg + ((size_t)(n * BN + r)) * rs + c4 * 4);
            *(float4*)(Vs + r * VS + c4 * 4) = vv;
        }
        __syncthreads();

        const int nBase = n * BN;
        if (nBase <= m * BM + R0 + 15) {       // warp has at least one visible col
            // ---- S = Q K^T via 3xTF32 mma ----
            float s[8][4];
#pragma unroll
            for (int j = 0; j < 8; ++j) { s[j][0] = s[j][1] = s[j][2] = s[j][3] = 0.f; }

#pragma unroll
            for (int cc = 0; cc < 8; ++cc) {
                uint32_t qh[4], ql[4];
#pragma unroll
                for (int e = 0; e < 4; ++e) tf32_split(qf[cc][e], qh[e], ql[e]);
#pragma unroll
                for (int j = 0; j < 8; ++j) {
                    float k0 = Ks[(8 * j + g) * KS + 8 * cc + tg];
                    float k1 = Ks[(8 * j + g) * KS + 8 * cc + tg + 4];
                    uint32_t kh0, kl0, kh1, kl1;
                    tf32_split(k0, kh0, kl0);
                    tf32_split(k1, kh1, kl1);
                    mma8(s[j], qh[0], qh[1], qh[2], qh[3], kh0, kh1);
                    mma8(s[j], qh[0], qh[1], qh[2], qh[3], kl0, kl1);
                    mma8(s[j], ql[0], ql[1], ql[2], ql[3], kh0, kh1);
                }
            }

            // ---- Causal mask (only blocks touching the diagonal) ----
            if (nBase + BN - 1 > gRowA) {
#pragma unroll
                for (int j = 0; j < 8; ++j) {
                    int c0 = nBase + 8 * j + 2 * tg;
                    if (c0     > gRowA) s[j][0] = -1e30f;
                    if (c0 + 1 > gRowA) s[j][1] = -1e30f;
                    if (c0     > gRowB) s[j][2] = -1e30f;
                    if (c0 + 1 > gRowB) s[j][3] = -1e30f;
                }
            }

            // ---- Online softmax: rows A (g) and B (g+8); 4-lane row groups ----
            float tA = s[0][0], tB = s[0][2];
#pragma unroll
            for (int j = 0; j < 8; ++j) {
                tA = fmaxf(tA, fmaxf(s[j][0], s[j][1]));
                tB = fmaxf(tB, fmaxf(s[j][2], s[j][3]));
            }
            tA = fmaxf(tA, __shfl_xor_sync(0xffffffffu, tA, 1));
            tA = fmaxf(tA, __shfl_xor_sync(0xffffffffu, tA, 2));
            tB = fmaxf(tB, __shfl_xor_sync(0xffffffffu, tB, 1));
            tB = fmaxf(tB, __shfl_xor_sync(0xffffffffu, tB, 2));
            float mnA = fmaxf(mA, tA), mnB = fmaxf(mB, tB);
            float scA = __expf(mA - mnA), scB = __expf(mB - mnB);
            float rsA = 0.f, rsB = 0.f;
#pragma unroll
            for (int j = 0; j < 8; ++j) {
                s[j][0] = __expf(s[j][0] - mnA);
                s[j][1] = __expf(s[j][1] - mnA);
                s[j][2] = __expf(s[j][2] - mnB);
                s[j][3] = __expf(s[j][3] - mnB);
                rsA += s[j][0] + s[j][1];
                rsB += s[j][2] + s[j][3];
            }
            rsA += __shfl_xor_sync(0xffffffffu, rsA, 1);
            rsA += __shfl_xor_sync(0xffffffffu, rsA, 2);
            rsB += __shfl_xor_sync(0xffffffffu, rsB, 1);
            rsB += __shfl_xor_sync(0xffffffffu, rsB, 2);
            lA = lA * scA + rsA;  mA = mnA;
            lB = lB * scB + rsB;  mB = mnB;
#pragma unroll
            for (int j = 0; j < 8; ++j) {
                o[j][0] *= scA; o[j][1] *= scA;
                o[j][2] *= scB; o[j][3] *= scB;
            }

            // ---- Stage P (warp-private), C-layout -> smem ----
            __syncwarp();
#pragma unroll
            for (int j = 0; j < 8; ++j) {
                *(float2*)(Pw + g       * PS + 8 * j + 2 * tg) = make_float2(s[j][0], s[j][1]);
                *(float2*)(Pw + (g + 8) * PS + 8 * j + 2 * tg) = make_float2(s[j][2], s[j][3]);
            }
            __syncwarp();

            // ---- O += P V via 3xTF32 mma ----
#pragma unroll
            for (int cc = 0; cc < 8; ++cc) {
                float p0 = Pw[g       * PS + 8 * cc + tg];
                float p1 = Pw[(g + 8) * PS + 8 * cc + tg];
                float p2 = Pw[g       * PS + 8 * cc + tg + 4];
                float p3 = Pw[(g + 8) * PS + 8 * cc + tg + 4];
                uint32_t ah[4], al[4];
                tf32_split(p0, ah[0], al[0]);
                tf32_split(p1, ah[1], al[1]);
                tf32_split(p2, ah[2], al[2]);
                tf32_split(p3, ah[3], al[3]);
#pragma unroll
                for (int j = 0; j < 8; ++j) {
                    float v0 = Vs[(8 * cc + tg)     * VS + 8 * j + g];
                    float v1 = Vs[(8 * cc + tg + 4) * VS + 8 * j + g];
                    uint32_t vh0, vl0, vh1, vl1;
                    tf32_split(v0, vh0, vl0);
                    tf32_split(v1, vh1, vl1);
                    mma8(o[j], ah[0], ah[1], ah[2], ah[3], vh0, vh1);
                    mma8(o[j], ah[0], ah[1], ah[2], ah[3], vl0, vl1);
                    mma8(o[j], al[0], al[1], al[2], al[3], vh0, vh1);
                }
            }
        }
    }

    // ---- Epilogue: normalize, store (output [B, H, L, D]) ----
    float* Og = O + ((size_t)(b * Hc + h) * Lc + (size_t)m * BM) * Dc;
    float invA = 1.f / lA, invB = 1.f / lB;
#pragma unroll
    for (int j = 0; j < 8; ++j) {
        int c = 8 * j + 2 * tg;
        *(float2*)(Og + (size_t)(R0 + g)     * Dc + c) = make_float2(o[j][0] * invA, o[j][1] * invA);
        *(float2*)(Og + (size_t)(R0 + g + 8) * Dc + c) = make_float2(o[j][2] * invB, o[j][3] * invB);
    }
}

extern "C" void kernel_launch(void* const* d_in, const int* in_sizes, int n_in,
                              void* d_out, int out_size) {
    const float* Q = (const float*)d_in[0];
    const float* K = (const float*)d_in[1];
    const float* V = (const float*)d_in[2];
    float* O = (float*)d_out;

    cudaFuncSetAttribute(logsparse_flash_tc_kernel,
                         cudaFuncAttributeMaxDynamicSharedMemorySize, SMEM_BYTES);

    dim3 grid(Lc / BM, Bc * Hc);
    logsparse_flash_tc_kernel<<<grid, NT, SMEM_BYTES>>>(Q, K, V, O);
}